// round 10
// baseline (speedup 1.0000x reference)
#include <cuda_runtime.h>
#include <cuda_fp16.h>
#include <cstdint>
#include <cstddef>

#define D 128
#define MAXN 50000
#define MAXE 600064
#define SCAN_B 256

// ---- scratch (allocation-free: __device__ globals) ----
__device__ int    g_cnt_out[MAXN];
__device__ int    g_cnt_in[MAXN];
__device__ float  g_norm_src[MAXN];
__device__ float  g_norm_dst[MAXN];
__device__ int    g_row_start[MAXN];
__device__ int    g_cursor[MAXN];
__device__ int    g_sorted_src[MAXE];
__device__ __half g_hf16[(size_t)MAXN * D];    // fp16 gather operand, PRE-SCALED by norm_src
__device__ __half g_agg16[(size_t)MAXN * D];   // fp16 aggregation buffer

__global__ void k_zero2i(int* a, int* b, int n) {
    int i = blockIdx.x * blockDim.x + threadIdx.x;
    if (i < n) { a[i] = 0; b[i] = 0; }
}

__global__ void k_hist(const int* __restrict__ src, const int* __restrict__ dst,
                       int* __restrict__ cnt_out, int* __restrict__ cnt_in, int E) {
    int i = blockIdx.x * blockDim.x + threadIdx.x;
    if (i < E) {
        atomicAdd(&cnt_out[src[i]], 1);
        atomicAdd(&cnt_in[dst[i]], 1);
    }
}

// ---- merged: exclusive scan of cnt_in (direct prefix re-read) + norms + fp16 mirror ----
__global__ __launch_bounds__(SCAN_B)
void k_csr_prep(const int* __restrict__ cnt_out, const int* __restrict__ cnt_in,
                const float* __restrict__ features,
                int* __restrict__ row_start, int* __restrict__ cursor,
                float* __restrict__ nsrc, float* __restrict__ ndst,
                __half* __restrict__ hf16, int N) {
    __shared__ int sh[SCAN_B];
    __shared__ float sh_ns[SCAN_B];
    const int tid = threadIdx.x;
    const int b = blockIdx.x;
    const int warp = tid >> 5;
    const int lane = tid & 31;

    // phase A: prefix over all previous blocks' cnt_in
    int partial = 0;
    int lim = b * SCAN_B;
    for (int j = tid; j < lim; j += SCAN_B) partial += __ldg(&cnt_in[j]);
    sh[tid] = partial; __syncthreads();
#pragma unroll
    for (int off = 128; off > 0; off >>= 1) {
        if (tid < off) sh[tid] += sh[tid + off];
        __syncthreads();
    }
    int prefix = sh[0];
    __syncthreads();

    // phase B: in-block inclusive scan of this block's 256 counts
    int i = b * SCAN_B + tid;
    int v = (i < N) ? __ldg(&cnt_in[i]) : 0;
    sh[tid] = v; __syncthreads();
#pragma unroll
    for (int off = 1; off < SCAN_B; off <<= 1) {
        int t = (tid >= off) ? sh[tid - off] : 0;
        __syncthreads();
        sh[tid] += t;
        __syncthreads();
    }
    float ns = 0.f;
    if (i < N) {
        int r = prefix + sh[tid] - v;
        row_start[i] = r;
        cursor[i] = r;
        ns = rsqrtf(fmaxf((float)__ldg(&cnt_out[i]), 1.f));
        nsrc[i] = ns;
        ndst[i] = rsqrtf(fmaxf((float)v, 1.f));
    }
    sh_ns[tid] = ns;
    __syncthreads();

    // phase C: fp16 mirror of this block's feature rows, pre-scaled by nsrc (warp per row)
    for (int rr = warp; rr < SCAN_B; rr += 8) {
        int row = b * SCAN_B + rr;
        if (row >= N) break;
        float s = sh_ns[rr];
        float4 f = __ldg((const float4*)(features + (size_t)row * D) + lane);
        __half2 h0 = __floats2half2_rn(f.x * s, f.y * s);
        __half2 h1 = __floats2half2_rn(f.z * s, f.w * s);
        uint2 u;
        u.x = *(uint32_t*)&h0;
        u.y = *(uint32_t*)&h1;
        *((uint2*)(hf16 + (size_t)row * D) + lane) = u;
    }
}

// ---- bucket edges by dst: CSR src list ----
__global__ void k_bucket(const int* __restrict__ src, const int* __restrict__ dst,
                         int* __restrict__ cursor, int* __restrict__ sorted_src, int E) {
    int i = blockIdx.x * blockDim.x + threadIdx.x;
    if (i < E) {
        int pos = atomicAdd(&cursor[dst[i]], 1);
        sorted_src[pos] = src[i];
    }
}

// ---- add 8 halves (uint4) into 8 fp32 accumulators ----
__device__ __forceinline__ void acc_add8(float* acc, uint4 u) {
    float2 p0 = __half22float2(*(__half2*)&u.x);
    float2 p1 = __half22float2(*(__half2*)&u.y);
    float2 p2 = __half22float2(*(__half2*)&u.z);
    float2 p3 = __half22float2(*(__half2*)&u.w);
    acc[0] += p0.x; acc[1] += p0.y;
    acc[2] += p1.x; acc[3] += p1.y;
    acc[4] += p2.x; acc[5] += p2.y;
    acc[6] += p3.x; acc[7] += p3.y;
}

// ---- atomic-free aggregation: HALF-WARP per dst node; fp16 in, fp16 out ----
__global__ void k_gather16(const __half* __restrict__ hf, const int* __restrict__ sorted_src,
                           const int* __restrict__ row_start, const int* __restrict__ cnt_in,
                           __half* __restrict__ agg, int N) {
    int n = (blockIdx.x * blockDim.x + threadIdx.x) >> 4;
    int lane = threadIdx.x & 15;
    if (n >= N) return;
    int start = __ldg(&row_start[n]);
    int cnt = __ldg(&cnt_in[n]);
    float acc[8] = {0.f, 0.f, 0.f, 0.f, 0.f, 0.f, 0.f, 0.f};
    const int* sp = sorted_src + start;
    int j = 0;
    for (; j + 4 <= cnt; j += 4) {
        int s0 = __ldg(sp + j);
        int s1 = __ldg(sp + j + 1);
        int s2 = __ldg(sp + j + 2);
        int s3 = __ldg(sp + j + 3);
        uint4 u0 = __ldg((const uint4*)(hf + (size_t)s0 * D) + lane);
        uint4 u1 = __ldg((const uint4*)(hf + (size_t)s1 * D) + lane);
        uint4 u2 = __ldg((const uint4*)(hf + (size_t)s2 * D) + lane);
        uint4 u3 = __ldg((const uint4*)(hf + (size_t)s3 * D) + lane);
        acc_add8(acc, u0); acc_add8(acc, u1); acc_add8(acc, u2); acc_add8(acc, u3);
    }
    for (; j < cnt; j++) {
        int s = __ldg(sp + j);
        uint4 u = __ldg((const uint4*)(hf + (size_t)s * D) + lane);
        acc_add8(acc, u);
    }
    __half2 h0 = __floats2half2_rn(acc[0], acc[1]);
    __half2 h1 = __floats2half2_rn(acc[2], acc[3]);
    __half2 h2 = __floats2half2_rn(acc[4], acc[5]);
    __half2 h3 = __floats2half2_rn(acc[6], acc[7]);
    uint4 o;
    o.x = *(uint32_t*)&h0; o.y = *(uint32_t*)&h1;
    o.z = *(uint32_t*)&h2; o.w = *(uint32_t*)&h3;
    *((uint4*)(agg + (size_t)n * D) + lane) = o;
}

// ---- tf32 helpers ----
__device__ __forceinline__ uint32_t f2tf32(float x) {
    uint32_t r;
    asm("cvt.rna.tf32.f32 %0, %1;" : "=r"(r) : "f"(x));
    return r;
}

__device__ __forceinline__ void mma_tf32(float* c, uint32_t a0, uint32_t a1,
                                         uint32_t a2, uint32_t a3,
                                         uint32_t b0, uint32_t b1) {
    asm volatile(
        "mma.sync.aligned.m16n8k8.row.col.f32.tf32.tf32.f32 "
        "{%0,%1,%2,%3}, {%4,%5,%6,%7}, {%8,%9}, {%0,%1,%2,%3};"
        : "+f"(c[0]), "+f"(c[1]), "+f"(c[2]), "+f"(c[3])
        : "r"(a0), "r"(a1), "r"(a2), "r"(a3), "r"(b0), "r"(b1));
}

// ---- fused: C = relu((A16 * ndst[:,None]) @ W + b); A16 is fp16 ----
// HALF_OUT: also emit fp16 copy pre-scaled by nsrc (next layer's gather operand).
#define AS_STRIDE 36
#define WS_STRIDE 136

template <bool HALF_OUT>
__global__ __launch_bounds__(256)
void k_gemm_tf32(const __half* __restrict__ A16, const float* __restrict__ Wm,
                 const float* __restrict__ bias, const float* __restrict__ norm,
                 const float* __restrict__ nsrc,
                 float* __restrict__ C, __half* __restrict__ C16, int N) {
    __shared__ uint32_t As[128 * AS_STRIDE];
    __shared__ uint32_t Ws[32 * WS_STRIDE];

    const int tid = threadIdx.x;
    const int warp = tid >> 5;
    const int lane = tid & 31;
    const int g = lane >> 2;
    const int t = lane & 3;
    const int row0 = blockIdx.x * 128;

    float acc[16][4];
#pragma unroll
    for (int j = 0; j < 16; j++)
#pragma unroll
        for (int i = 0; i < 4; i++) acc[j][i] = 0.f;

    for (int kt = 0; kt < 128; kt += 32) {
        // stage W k-tile [32][128] -> Ws (tf32)
#pragma unroll
        for (int j = 0; j < 4; j++) {
            int f = tid + j * 256;
            int kk = f >> 5;
            int c4 = f & 31;
            float4 w = __ldg((const float4*)&Wm[(size_t)(kt + kk) * 128 + c4 * 4]);
            uint32_t* p = &Ws[kk * WS_STRIDE + c4 * 4];
            p[0] = f2tf32(w.x); p[1] = f2tf32(w.y); p[2] = f2tf32(w.z); p[3] = f2tf32(w.w);
        }
        // stage A k-tile [128][32] from fp16 -> As (tf32, ndst fused)
#pragma unroll
        for (int j = 0; j < 4; j++) {
            int f = tid + j * 256;
            int rr = f >> 3;
            int c4 = f & 7;
            int grow = row0 + rr;
            float4 a = make_float4(0.f, 0.f, 0.f, 0.f);
            if (grow < N) {
                uint2 u = __ldg((const uint2*)(A16 + (size_t)grow * D + kt) + c4);
                float2 p0 = __half22float2(*(__half2*)&u.x);
                float2 p1 = __half22float2(*(__half2*)&u.y);
                float nm = __ldg(&norm[grow]);
                a.x = p0.x * nm; a.y = p0.y * nm;
                a.z = p1.x * nm; a.w = p1.y * nm;
            }
            uint32_t* p = &As[rr * AS_STRIDE + c4 * 4];
            p[0] = f2tf32(a.x); p[1] = f2tf32(a.y); p[2] = f2tf32(a.z); p[3] = f2tf32(a.w);
        }
        __syncthreads();

#pragma unroll
        for (int k8 = 0; k8 < 4; k8++) {
            int kb = k8 * 8;
            int r = warp * 16;
            uint32_t a0 = As[(r + g) * AS_STRIDE + kb + t];
            uint32_t a1 = As[(r + g + 8) * AS_STRIDE + kb + t];
            uint32_t a2 = As[(r + g) * AS_STRIDE + kb + t + 4];
            uint32_t a3 = As[(r + g + 8) * AS_STRIDE + kb + t + 4];
#pragma unroll
            for (int j = 0; j < 16; j++) {
                uint32_t b0 = Ws[(kb + t) * WS_STRIDE + j * 8 + g];
                uint32_t b1 = Ws[(kb + t + 4) * WS_STRIDE + j * 8 + g];
                mma_tf32(acc[j], a0, a1, a2, a3, b0, b1);
            }
        }
        __syncthreads();
    }

    const int r1 = row0 + warp * 16 + g;
    const int r2 = r1 + 8;
    float ns1 = 1.f, ns2 = 1.f;
    if (HALF_OUT) {
        if (r1 < N) ns1 = __ldg(&nsrc[r1]);
        if (r2 < N) ns2 = __ldg(&nsrc[r2]);
    }
#pragma unroll
    for (int j = 0; j < 16; j++) {
        int col = j * 8 + 2 * t;
        float2 bv = *(const float2*)&bias[col];
        float2 o1, o2;
        o1.x = fmaxf(acc[j][0] + bv.x, 0.f);
        o1.y = fmaxf(acc[j][1] + bv.y, 0.f);
        o2.x = fmaxf(acc[j][2] + bv.x, 0.f);
        o2.y = fmaxf(acc[j][3] + bv.y, 0.f);
        if (HALF_OUT) {
            if (r1 < N) {
                __half2 h = __floats2half2_rn(o1.x * ns1, o1.y * ns1);
                *(__half2*)&C16[(size_t)r1 * 128 + col] = h;
            }
            if (r2 < N) {
                __half2 h = __floats2half2_rn(o2.x * ns2, o2.y * ns2);
                *(__half2*)&C16[(size_t)r2 * 128 + col] = h;
            }
        } else {
            if (r1 < N) *(float2*)&C[(size_t)r1 * 128 + col] = o1;
            if (r2 < N) *(float2*)&C[(size_t)r2 * 128 + col] = o2;
        }
    }
}

extern "C" void kernel_launch(void* const* d_in, const int* in_sizes, int n_in,
                              void* d_out, int out_size) {
    const float* features = (const float*)d_in[0];
    const int* src = (const int*)d_in[1];
    const int* dst = (const int*)d_in[2];
    const float* W1 = (const float*)d_in[3];
    const float* b1 = (const float*)d_in[4];
    const float* W2 = (const float*)d_in[5];
    const float* b2 = (const float*)d_in[6];
    float* out = (float*)d_out;

    int N = in_sizes[0] / D;
    int E = in_sizes[1];

    int *cnt_out, *cnt_in, *row_start, *cursor, *sorted_src;
    float *nsrc, *ndst;
    __half *hf16, *agg16;
    cudaGetSymbolAddress((void**)&cnt_out, g_cnt_out);
    cudaGetSymbolAddress((void**)&cnt_in, g_cnt_in);
    cudaGetSymbolAddress((void**)&row_start, g_row_start);
    cudaGetSymbolAddress((void**)&cursor, g_cursor);
    cudaGetSymbolAddress((void**)&sorted_src, g_sorted_src);
    cudaGetSymbolAddress((void**)&nsrc, g_norm_src);
    cudaGetSymbolAddress((void**)&ndst, g_norm_dst);
    cudaGetSymbolAddress((void**)&hf16, g_hf16);
    cudaGetSymbolAddress((void**)&agg16, g_agg16);

    const int ZB = 256;
    int nblkN = (N + ZB - 1) / ZB;
    int nblkE = (E + ZB - 1) / ZB;

    // 8 launches total
    k_zero2i<<<nblkN, ZB>>>(cnt_out, cnt_in, N);
    k_hist<<<nblkE, ZB>>>(src, dst, cnt_out, cnt_in, E);
    k_csr_prep<<<nblkN, SCAN_B>>>(cnt_out, cnt_in, features, row_start, cursor,
                                  nsrc, ndst, hf16, N);
    k_bucket<<<nblkE, ZB>>>(src, dst, cursor, sorted_src, E);

    int gath_blocks = (N * 16 + ZB - 1) / ZB;
    int gemm_blocks = (N + 127) / 128;

    // layer 1: sum pre-scaled fp16 rows -> agg16; GEMM -> h1 (fp16, pre-scaled by nsrc)
    k_gather16<<<gath_blocks, ZB>>>(hf16, sorted_src, row_start, cnt_in, agg16, N);
    k_gemm_tf32<true><<<gemm_blocks, 256>>>(agg16, W1, b1, ndst, nsrc, nullptr, hf16, N);

    // layer 2: sum pre-scaled fp16 h1 rows -> agg16; GEMM -> fp32 out
    k_gather16<<<gath_blocks, ZB>>>(hf16, sorted_src, row_start, cnt_in, agg16, N);
    k_gemm_tf32<false><<<gemm_blocks, 256>>>(agg16, W2, b2, ndst, nullptr, out, nullptr, N);
}

// round 11
// speedup vs baseline: 1.2702x; 1.2702x over previous
#include <cuda_runtime.h>
#include <cuda_fp16.h>
#include <cstdint>
#include <cstddef>

#define D 128
#define MAXN 50000
#define MAXE 600064
#define SCAN_B 256

// ---- scratch (allocation-free: __device__ globals) ----
__device__ int    g_cnt_out[MAXN];
__device__ int    g_cnt_in[MAXN];
__device__ float  g_norm_src[MAXN];
__device__ float  g_norm_dst[MAXN];
__device__ int    g_row_start[MAXN];
__device__ int    g_cursor[MAXN];
__device__ int    g_blk_sums[SCAN_B];
__device__ int    g_sorted_src[MAXE];
__device__ __half g_hf16[(size_t)MAXN * D];    // fp16 gather operand, PRE-SCALED by norm_src
__device__ __half g_agg16[(size_t)MAXN * D];   // fp16 aggregation buffer (ndst-scaled)
__device__ __half g_w1t[D * D];                // W1^T fp16 [col][k]
__device__ __half g_w2t[D * D];                // W2^T fp16 [col][k]

__global__ void k_zero2i(int* a, int* b, int n) {
    int i = blockIdx.x * blockDim.x + threadIdx.x;
    if (i < n) { a[i] = 0; b[i] = 0; }
}

__global__ void k_hist(const int* __restrict__ src, const int* __restrict__ dst,
                       int* __restrict__ cnt_out, int* __restrict__ cnt_in, int E) {
    int i = blockIdx.x * blockDim.x + threadIdx.x;
    if (i < E) {
        atomicAdd(&cnt_out[src[i]], 1);
        atomicAdd(&cnt_in[dst[i]], 1);
    }
}

// ---- fp32 features -> fp16 mirror pre-scaled by norm_src; warp per row ----
__global__ void k_f2h_scaled(const float* __restrict__ in, const float* __restrict__ nsrc,
                             __half* __restrict__ out, int N) {
    int row = (blockIdx.x * blockDim.x + threadIdx.x) >> 5;
    int lane = threadIdx.x & 31;
    if (row >= N) return;
    float ns = __ldg(&nsrc[row]);
    float4 v = __ldg((const float4*)(in + (size_t)row * D) + lane);
    __half2 h0 = __floats2half2_rn(v.x * ns, v.y * ns);
    __half2 h1 = __floats2half2_rn(v.z * ns, v.w * ns);
    uint2 u;
    u.x = *(uint32_t*)&h0;
    u.y = *(uint32_t*)&h1;
    *((uint2*)(out + (size_t)row * D) + lane) = u;
}

// ---- transpose W (fp32 [k][n]) -> Wt (fp16 [n][k]); grid (4,4,2), block (32,8) ----
__global__ void k_prep_wt(const float* __restrict__ W1, const float* __restrict__ W2,
                          __half* __restrict__ W1t, __half* __restrict__ W2t) {
    __shared__ float tile[32][33];
    const float* W = blockIdx.z ? W2 : W1;
    __half* Wt = blockIdx.z ? W2t : W1t;
    int k0 = blockIdx.x * 32;
    int c0 = blockIdx.y * 32;
    int tx = threadIdx.x, ty = threadIdx.y;
#pragma unroll
    for (int i = 0; i < 4; i++) {
        int k = ty + i * 8;
        tile[k][tx] = __ldg(&W[(size_t)(k0 + k) * D + c0 + tx]);
    }
    __syncthreads();
#pragma unroll
    for (int i = 0; i < 4; i++) {
        int c = ty + i * 8;
        Wt[(size_t)(c0 + c) * D + k0 + tx] = __float2half_rn(tile[tx][c]);
    }
}

// ---- block-level exclusive scan of cnt_in ----
__global__ void k_scan_block(const int* __restrict__ cnt, int* __restrict__ excl,
                             int* __restrict__ blk_sums, int N) {
    __shared__ int sh[SCAN_B];
    int i = blockIdx.x * SCAN_B + threadIdx.x;
    int v = (i < N) ? cnt[i] : 0;
    sh[threadIdx.x] = v; __syncthreads();
#pragma unroll
    for (int off = 1; off < SCAN_B; off <<= 1) {
        int t = (threadIdx.x >= off) ? sh[threadIdx.x - off] : 0;
        __syncthreads();
        sh[threadIdx.x] += t;
        __syncthreads();
    }
    if (i < N) excl[i] = sh[threadIdx.x] - v;
    if (threadIdx.x == SCAN_B - 1) blk_sums[blockIdx.x] = sh[SCAN_B - 1];
}

// ---- finish scan (per-block prefix reduce) + norms ----
__global__ void k_scan_add_norm(int* __restrict__ excl, const int* __restrict__ blk_sums,
                                int* __restrict__ cursor,
                                const int* __restrict__ cnt_out, const int* __restrict__ cnt_in,
                                float* __restrict__ nsrc, float* __restrict__ ndst,
                                int nb, int N) {
    __shared__ int sh[SCAN_B];
    int v = (threadIdx.x < blockIdx.x && threadIdx.x < nb) ? blk_sums[threadIdx.x] : 0;
    sh[threadIdx.x] = v; __syncthreads();
#pragma unroll
    for (int off = 128; off > 0; off >>= 1) {
        if (threadIdx.x < off) sh[threadIdx.x] += sh[threadIdx.x + off];
        __syncthreads();
    }
    int prefix = sh[0];
    int i = blockIdx.x * SCAN_B + threadIdx.x;
    if (i < N) {
        int r = excl[i] + prefix;
        excl[i] = r;
        cursor[i] = r;
        nsrc[i] = rsqrtf(fmaxf((float)cnt_out[i], 1.f));
        ndst[i] = rsqrtf(fmaxf((float)cnt_in[i], 1.f));
    }
}

// ---- bucket edges by dst: CSR src list ----
__global__ void k_bucket(const int* __restrict__ src, const int* __restrict__ dst,
                         int* __restrict__ cursor, int* __restrict__ sorted_src, int E) {
    int i = blockIdx.x * blockDim.x + threadIdx.x;
    if (i < E) {
        int pos = atomicAdd(&cursor[dst[i]], 1);
        sorted_src[pos] = src[i];
    }
}

// ---- add 8 halves (uint4) into 8 fp32 accumulators ----
__device__ __forceinline__ void acc_add8(float* acc, uint4 u) {
    float2 p0 = __half22float2(*(__half2*)&u.x);
    float2 p1 = __half22float2(*(__half2*)&u.y);
    float2 p2 = __half22float2(*(__half2*)&u.z);
    float2 p3 = __half22float2(*(__half2*)&u.w);
    acc[0] += p0.x; acc[1] += p0.y;
    acc[2] += p1.x; acc[3] += p1.y;
    acc[4] += p2.x; acc[5] += p2.y;
    acc[6] += p3.x; acc[7] += p3.y;
}

// ---- atomic-free aggregation: HALF-WARP per dst node; applies ndst; fp16 out ----
__global__ void k_gather16(const __half* __restrict__ hf, const int* __restrict__ sorted_src,
                           const int* __restrict__ row_start, const int* __restrict__ cnt_in,
                           const float* __restrict__ ndst, __half* __restrict__ agg, int N) {
    int n = (blockIdx.x * blockDim.x + threadIdx.x) >> 4;
    int lane = threadIdx.x & 15;
    if (n >= N) return;
    int start = __ldg(&row_start[n]);
    int cnt = __ldg(&cnt_in[n]);
    float acc[8] = {0.f, 0.f, 0.f, 0.f, 0.f, 0.f, 0.f, 0.f};
    const int* sp = sorted_src + start;
    int j = 0;
    for (; j + 4 <= cnt; j += 4) {
        int s0 = __ldg(sp + j);
        int s1 = __ldg(sp + j + 1);
        int s2 = __ldg(sp + j + 2);
        int s3 = __ldg(sp + j + 3);
        uint4 u0 = __ldg((const uint4*)(hf + (size_t)s0 * D) + lane);
        uint4 u1 = __ldg((const uint4*)(hf + (size_t)s1 * D) + lane);
        uint4 u2 = __ldg((const uint4*)(hf + (size_t)s2 * D) + lane);
        uint4 u3 = __ldg((const uint4*)(hf + (size_t)s3 * D) + lane);
        acc_add8(acc, u0); acc_add8(acc, u1); acc_add8(acc, u2); acc_add8(acc, u3);
    }
    for (; j < cnt; j++) {
        int s = __ldg(sp + j);
        uint4 u = __ldg((const uint4*)(hf + (size_t)s * D) + lane);
        acc_add8(acc, u);
    }
    float nd = __ldg(&ndst[n]);
    __half2 h0 = __floats2half2_rn(acc[0] * nd, acc[1] * nd);
    __half2 h1 = __floats2half2_rn(acc[2] * nd, acc[3] * nd);
    __half2 h2 = __floats2half2_rn(acc[4] * nd, acc[5] * nd);
    __half2 h3 = __floats2half2_rn(acc[6] * nd, acc[7] * nd);
    uint4 o;
    o.x = *(uint32_t*)&h0; o.y = *(uint32_t*)&h1;
    o.z = *(uint32_t*)&h2; o.w = *(uint32_t*)&h3;
    *((uint4*)(agg + (size_t)n * D) + lane) = o;
}

// ---- fp16 mma m16n8k16, fp32 accumulate ----
__device__ __forceinline__ void mma_f16(float* c, uint32_t a0, uint32_t a1,
                                        uint32_t a2, uint32_t a3,
                                        uint32_t b0, uint32_t b1) {
    asm volatile(
        "mma.sync.aligned.m16n8k16.row.col.f32.f16.f16.f32 "
        "{%0,%1,%2,%3}, {%4,%5,%6,%7}, {%8,%9}, {%0,%1,%2,%3};"
        : "+f"(c[0]), "+f"(c[1]), "+f"(c[2]), "+f"(c[3])
        : "r"(a0), "r"(a1), "r"(a2), "r"(a3), "r"(b0), "r"(b1));
}

// ---- fp16 GEMM: C = relu(A16 @ Wt^T + b); A16 already ndst-scaled fp16 ----
// block 256 threads (8 warps), tile 128 x 128, full tiles staged once.
// SMEM stride 68 u32 per row -> fragment banks 4g+t+8ks (conflict-free).
#define S68 68

template <bool HALF_OUT>
__global__ __launch_bounds__(256)
void k_gemm_f16(const __half* __restrict__ A16, const __half* __restrict__ Wt,
                const float* __restrict__ bias, const float* __restrict__ nsrc,
                float* __restrict__ C, __half* __restrict__ C16, int N) {
    extern __shared__ uint32_t sh[];
    uint32_t* As = sh;              // 128 rows x 68 u32
    uint32_t* Ws = sh + 128 * S68;  // 128 cols x 68 u32

    const int tid = threadIdx.x;
    const int warp = tid >> 5;
    const int lane = tid & 31;
    const int g = lane >> 2;
    const int t = lane & 3;
    const int row0 = blockIdx.x * 128;

    // stage A: 128 rows x 16 uint4 (raw fp16 copy)
#pragma unroll
    for (int j = 0; j < 8; j++) {
        int f = tid + j * 256;
        int row = f >> 4;
        int c4 = f & 15;
        int grow = row0 + row;
        uint4 v = make_uint4(0u, 0u, 0u, 0u);
        if (grow < N) v = __ldg((const uint4*)(A16 + (size_t)grow * D) + c4);
        *(uint4*)&As[row * S68 + c4 * 4] = v;
    }
    // stage Wt: 128 cols x 16 uint4 (raw fp16 copy)
#pragma unroll
    for (int j = 0; j < 8; j++) {
        int f = tid + j * 256;
        int col = f >> 4;
        int c4 = f & 15;
        uint4 v = __ldg((const uint4*)(Wt + (size_t)col * D) + c4);
        *(uint4*)&Ws[col * S68 + c4 * 4] = v;
    }
    __syncthreads();

    float acc[16][4];
#pragma unroll
    for (int j = 0; j < 16; j++)
#pragma unroll
        for (int i = 0; i < 4; i++) acc[j][i] = 0.f;

    const int r = warp * 16;
#pragma unroll
    for (int ks = 0; ks < 8; ks++) {
        int ko = ks * 8 + t;
        uint32_t a0 = As[(r + g) * S68 + ko];
        uint32_t a1 = As[(r + g + 8) * S68 + ko];
        uint32_t a2 = As[(r + g) * S68 + ko + 4];
        uint32_t a3 = As[(r + g + 8) * S68 + ko + 4];
#pragma unroll
        for (int j = 0; j < 16; j++) {
            uint32_t b0 = Ws[(j * 8 + g) * S68 + ko];
            uint32_t b1 = Ws[(j * 8 + g) * S68 + ko + 4];
            mma_f16(acc[j], a0, a1, a2, a3, b0, b1);
        }
    }

    const int r1 = row0 + warp * 16 + g;
    const int r2 = r1 + 8;
    float ns1 = 1.f, ns2 = 1.f;
    if (HALF_OUT) {
        if (r1 < N) ns1 = __ldg(&nsrc[r1]);
        if (r2 < N) ns2 = __ldg(&nsrc[r2]);
    }
#pragma unroll
    for (int j = 0; j < 16; j++) {
        int col = j * 8 + 2 * t;
        float2 bv = *(const float2*)&bias[col];
        float2 o1, o2;
        o1.x = fmaxf(acc[j][0] + bv.x, 0.f);
        o1.y = fmaxf(acc[j][1] + bv.y, 0.f);
        o2.x = fmaxf(acc[j][2] + bv.x, 0.f);
        o2.y = fmaxf(acc[j][3] + bv.y, 0.f);
        if (HALF_OUT) {
            if (r1 < N) {
                __half2 h = __floats2half2_rn(o1.x * ns1, o1.y * ns1);
                *(__half2*)&C16[(size_t)r1 * D + col] = h;
            }
            if (r2 < N) {
                __half2 h = __floats2half2_rn(o2.x * ns2, o2.y * ns2);
                *(__half2*)&C16[(size_t)r2 * D + col] = h;
            }
        } else {
            if (r1 < N) *(float2*)&C[(size_t)r1 * D + col] = o1;
            if (r2 < N) *(float2*)&C[(size_t)r2 * D + col] = o2;
        }
    }
}

#define GEMM_SMEM (2 * 128 * S68 * 4)

extern "C" void kernel_launch(void* const* d_in, const int* in_sizes, int n_in,
                              void* d_out, int out_size) {
    const float* features = (const float*)d_in[0];
    const int* src = (const int*)d_in[1];
    const int* dst = (const int*)d_in[2];
    const float* W1 = (const float*)d_in[3];
    const float* b1 = (const float*)d_in[4];
    const float* W2 = (const float*)d_in[5];
    const float* b2 = (const float*)d_in[6];
    float* out = (float*)d_out;

    int N = in_sizes[0] / D;
    int E = in_sizes[1];

    int *cnt_out, *cnt_in, *row_start, *cursor, *blk_sums, *sorted_src;
    float *nsrc, *ndst;
    __half *hf16, *agg16, *w1t, *w2t;
    cudaGetSymbolAddress((void**)&cnt_out, g_cnt_out);
    cudaGetSymbolAddress((void**)&cnt_in, g_cnt_in);
    cudaGetSymbolAddress((void**)&row_start, g_row_start);
    cudaGetSymbolAddress((void**)&cursor, g_cursor);
    cudaGetSymbolAddress((void**)&blk_sums, g_blk_sums);
    cudaGetSymbolAddress((void**)&sorted_src, g_sorted_src);
    cudaGetSymbolAddress((void**)&nsrc, g_norm_src);
    cudaGetSymbolAddress((void**)&ndst, g_norm_dst);
    cudaGetSymbolAddress((void**)&hf16, g_hf16);
    cudaGetSymbolAddress((void**)&agg16, g_agg16);
    cudaGetSymbolAddress((void**)&w1t, g_w1t);
    cudaGetSymbolAddress((void**)&w2t, g_w2t);

    cudaFuncSetAttribute(k_gemm_f16<true>, cudaFuncAttributeMaxDynamicSharedMemorySize, GEMM_SMEM);
    cudaFuncSetAttribute(k_gemm_f16<false>, cudaFuncAttributeMaxDynamicSharedMemorySize, GEMM_SMEM);

    const int ZB = 256;
    int nblkN = (N + ZB - 1) / ZB;
    int nblkE = (E + ZB - 1) / ZB;

    // CSR build + norms + fp16 mirror + W transposes
    k_zero2i<<<nblkN, ZB>>>(cnt_out, cnt_in, N);
    k_hist<<<nblkE, ZB>>>(src, dst, cnt_out, cnt_in, E);
    k_scan_block<<<nblkN, SCAN_B>>>(cnt_in, row_start, blk_sums, N);
    k_scan_add_norm<<<nblkN, SCAN_B>>>(row_start, blk_sums, cursor,
                                       cnt_out, cnt_in, nsrc, ndst, nblkN, N);
    k_f2h_scaled<<<(N * 32 + ZB - 1) / ZB, ZB>>>(features, nsrc, hf16, N);
    k_prep_wt<<<dim3(4, 4, 2), dim3(32, 8)>>>(W1, W2, w1t, w2t);
    k_bucket<<<nblkE, ZB>>>(src, dst, cursor, sorted_src, E);

    int gath_blocks = (N * 16 + ZB - 1) / ZB;
    int gemm_blocks = (N + 127) / 128;

    // layer 1: gather (ndst-scaled fp16) -> agg16; fp16 GEMM -> h1 (fp16, nsrc-scaled)
    k_gather16<<<gath_blocks, ZB>>>(hf16, sorted_src, row_start, cnt_in, ndst, agg16, N);
    k_gemm_f16<true><<<gemm_blocks, 256, GEMM_SMEM>>>(agg16, w1t, b1, nsrc, nullptr, hf16, N);

    // layer 2: gather -> agg16; fp16 GEMM -> fp32 out
    k_gather16<<<gath_blocks, ZB>>>(hf16, sorted_src, row_start, cnt_in, ndst, agg16, N);
    k_gemm_f16<false><<<gemm_blocks, 256, GEMM_SMEM>>>(agg16, w2t, b2, nullptr, out, nullptr, N);
}